// round 1
// baseline (speedup 1.0000x reference)
#include <cuda_runtime.h>

#define FULL_MASK 0xffffffffu

static constexpr int NROWS = 65536;   // batch rows
static constexpr int KDIM  = 512;     // feature dim
static constexpr int MEM   = 2000;    // memory slots
static constexpr int MPAD  = 2048;    // padded mem dim
static constexpr int BM = 64;         // rows per CTA
static constexpr int BN = 128;        // mem-cols per CTA
static constexpr int BK = 16;         // k-chunk
static constexpr int NMBLK = MPAD / BN;   // 16 column blocks
static constexpr float LAMBDA = 0.0025f;

// Scratch (device globals: allocation-free per harness rules)
__device__ float g_E[(size_t)NROWS * MPAD];     // exp(logits), 512 MB
__device__ float g_Zp[NMBLK * NROWS];           // per-colblock row-sum partials

__device__ __forceinline__ unsigned long long pack2(float v) {
    unsigned long long r;
    asm("mov.b64 %0, {%1, %1};" : "=l"(r) : "f"(v));
    return r;
}
__device__ __forceinline__ void fma2(unsigned long long& d,
                                     unsigned long long a,
                                     unsigned long long b) {
    // packed f32x2 FMA: 2 FMAs/lane -> restores 128 FMA/cyc/SM
    asm("fma.rn.f32x2 %0, %1, %2, %0;" : "+l"(d) : "l"(a), "l"(b));
}
__device__ __forceinline__ float2 unpack2(unsigned long long v) {
    float lo, hi;
    asm("mov.b64 {%0, %1}, %2;" : "=f"(lo), "=f"(hi) : "l"(v));
    return make_float2(lo, hi);
}

// ---------------------------------------------------------------------------
// K1: logits = x @ W^T (fp32 via packed f32x2 FMA), E = exp(logit) -> g_E,
//     per-colblock row sums -> g_Zp. No atomics (deterministic).
// ---------------------------------------------------------------------------
__global__ void __launch_bounds__(256)
k_gemm_exp(const float* __restrict__ x, const float* __restrict__ w) {
    __shared__ __align__(16) float xs[2][BK][BM];
    __shared__ __align__(16) float ws[2][BK][BN];

    const int tid  = threadIdx.x;
    const int mblk = blockIdx.x;
    const int row0 = blockIdx.y * BM;
    const int col0 = mblk * BN;

    // loader mapping: 256 threads, float4 each
    const int lrow = tid >> 2;          // 0..63
    const int lk   = (tid & 3) * 4;     // 0,4,8,12

    // compute mapping: 8 warps; thread tile = 8 rows x 4 cols
    const int tx = tid & 31;
    const int ty = tid >> 5;
    const int r0 = ty * 8;
    const int c0 = tx * 4;

    unsigned long long acc[8][2];
    #pragma unroll
    for (int i = 0; i < 8; i++) { acc[i][0] = 0ull; acc[i][1] = 0ull; }

    const float* xg = x + (size_t)(row0 + lrow) * KDIM + lk;
    int wc0 = col0 + lrow;      if (wc0 >= MEM) wc0 = MEM - 1;   // clamp (masked later)
    int wc1 = col0 + lrow + 64; if (wc1 >= MEM) wc1 = MEM - 1;
    const float* wg0 = w + (size_t)wc0 * KDIM + lk;
    const float* wg1 = w + (size_t)wc1 * KDIM + lk;

    // stage chunk 0 (transposed to k-major for vector LDS)
    float4 xv  = *(const float4*)(xg);
    float4 wv0 = *(const float4*)(wg0);
    float4 wv1 = *(const float4*)(wg1);
    #pragma unroll
    for (int j = 0; j < 4; j++) {
        xs[0][lk + j][lrow]      = ((const float*)&xv)[j];
        ws[0][lk + j][lrow]      = ((const float*)&wv0)[j];
        ws[0][lk + j][lrow + 64] = ((const float*)&wv1)[j];
    }
    __syncthreads();

    for (int ch = 0; ch < KDIM / BK; ch++) {
        const int buf = ch & 1;
        if (ch + 1 < KDIM / BK) {         // prefetch next chunk into regs
            const int ko = (ch + 1) * BK;
            xv  = *(const float4*)(xg + ko);
            wv0 = *(const float4*)(wg0 + ko);
            wv1 = *(const float4*)(wg1 + ko);
        }
        #pragma unroll
        for (int kk = 0; kk < BK; kk++) {
            float4 xa = *(const float4*)&xs[buf][kk][r0];
            float4 xb = *(const float4*)&xs[buf][kk][r0 + 4];
            ulonglong2 wp = *(const ulonglong2*)&ws[buf][kk][c0];
            unsigned long long xp[8];
            xp[0] = pack2(xa.x); xp[1] = pack2(xa.y);
            xp[2] = pack2(xa.z); xp[3] = pack2(xa.w);
            xp[4] = pack2(xb.x); xp[5] = pack2(xb.y);
            xp[6] = pack2(xb.z); xp[7] = pack2(xb.w);
            #pragma unroll
            for (int i = 0; i < 8; i++) {
                fma2(acc[i][0], xp[i], wp.x);
                fma2(acc[i][1], xp[i], wp.y);
            }
        }
        if (ch + 1 < KDIM / BK) {         // store prefetched regs to other buffer
            const int nb = buf ^ 1;
            #pragma unroll
            for (int j = 0; j < 4; j++) {
                xs[nb][lk + j][lrow]      = ((const float*)&xv)[j];
                ws[nb][lk + j][lrow]      = ((const float*)&wv0)[j];
                ws[nb][lk + j][lrow + 64] = ((const float*)&wv1)[j];
            }
        }
        __syncthreads();
    }

    // epilogue: exp, mask padded cols, store E, per-row partial sums
    float rsum[8];
    #pragma unroll
    for (int i = 0; i < 8; i++) {
        const int grow = row0 + r0 + i;
        float2 p0 = unpack2(acc[i][0]);
        float2 p1 = unpack2(acc[i][1]);
        float e0 = expf(p0.x), e1 = expf(p0.y);
        float e2 = expf(p1.x), e3 = expf(p1.y);
        const int gc = col0 + c0;
        if (gc + 0 >= MEM) e0 = 0.f;
        if (gc + 1 >= MEM) e1 = 0.f;
        if (gc + 2 >= MEM) e2 = 0.f;
        if (gc + 3 >= MEM) e3 = 0.f;
        *(float4*)(g_E + (size_t)grow * MPAD + gc) = make_float4(e0, e1, e2, e3);
        rsum[i] = (e0 + e1) + (e2 + e3);
    }
    #pragma unroll
    for (int i = 0; i < 8; i++) {
        #pragma unroll
        for (int o = 16; o; o >>= 1)
            rsum[i] += __shfl_xor_sync(FULL_MASK, rsum[i], o);
    }
    if (tx == 0) {
        #pragma unroll
        for (int i = 0; i < 8; i++)
            g_Zp[mblk * NROWS + row0 + r0 + i] = rsum[i];
    }
}

// ---------------------------------------------------------------------------
// K2: per row (1 warp/row): Z = sum partials (fixed order), t = lambda*Z,
//     S = sum of survivors, att = E/S for survivors else 0,
//     out = sum_surv att_m * W[m]  (sparse: ~2 survivors/row).
// ---------------------------------------------------------------------------
__global__ void __launch_bounds__(256)
k_finish(const float* __restrict__ w, float* __restrict__ out,
         float* __restrict__ att) {
    const int lane = threadIdx.x & 31;
    const int wid  = threadIdx.x >> 5;
    const int n    = blockIdx.x * 8 + wid;

    const float4* E4 = (const float4*)(g_E + (size_t)n * MPAD);

    float Z = 0.f;
    #pragma unroll
    for (int j = 0; j < NMBLK; j++) Z += g_Zp[j * NROWS + n];
    const float t = LAMBDA * Z;

    // pass 1: survivor sum S (no sync ops inside -> divergent tail is fine)
    float s = 0.f;
    for (int i = lane; i < MEM / 4; i += 32) {
        float4 v = E4[i];
        if (v.x > t) s += v.x;
        if (v.y > t) s += v.y;
        if (v.z > t) s += v.z;
        if (v.w > t) s += v.w;
    }
    #pragma unroll
    for (int o = 16; o; o >>= 1) s += __shfl_xor_sync(FULL_MASK, s, o);
    const float inv = (s > 0.f) ? (1.0f / s) : 0.f;

    // pass 2: write att, accumulate sparse output (uniform trip count: shfl/ballot inside)
    float4* att4 = (float4*)(att + (size_t)n * MEM);
    float oacc[16];
    #pragma unroll
    for (int q = 0; q < 16; q++) oacc[q] = 0.f;

    for (int it = 0; it < 16; it++) {
        const int i = lane + 32 * it;
        const bool active = (i < MEM / 4);
        float4 v = active ? E4[i] : make_float4(0.f, 0.f, 0.f, 0.f);
        float4 o;
        int m4 = 0;
        o.x = (v.x > t) ? v.x * inv : 0.f; if (v.x > t) m4 |= 1;
        o.y = (v.y > t) ? v.y * inv : 0.f; if (v.y > t) m4 |= 2;
        o.z = (v.z > t) ? v.z * inv : 0.f; if (v.z > t) m4 |= 4;
        o.w = (v.w > t) ? v.w * inv : 0.f; if (v.w > t) m4 |= 8;
        if (active) att4[i] = o;

        unsigned bal = __ballot_sync(FULL_MASK, m4 != 0);
        while (bal) {
            const int src = __ffs(bal) - 1;
            bal &= bal - 1;
            const int sm4 = __shfl_sync(FULL_MASK, m4, src);
            float av[4];
            av[0] = __shfl_sync(FULL_MASK, o.x, src);
            av[1] = __shfl_sync(FULL_MASK, o.y, src);
            av[2] = __shfl_sync(FULL_MASK, o.z, src);
            av[3] = __shfl_sync(FULL_MASK, o.w, src);
            const int mbase = 4 * (src + 32 * it);
            #pragma unroll
            for (int j = 0; j < 4; j++) {
                if (sm4 & (1 << j)) {
                    const float* wr = w + (size_t)(mbase + j) * KDIM;
                    const float a = av[j];
                    #pragma unroll
                    for (int q = 0; q < 16; q++)
                        oacc[q] += a * wr[lane + 32 * q];
                }
            }
        }
    }

    float* orow = out + (size_t)n * KDIM;
    #pragma unroll
    for (int q = 0; q < 16; q++) orow[lane + 32 * q] = oacc[q];
}

// ---------------------------------------------------------------------------
extern "C" void kernel_launch(void* const* d_in, const int* in_sizes, int n_in,
                              void* d_out, int out_size) {
    (void)in_sizes; (void)n_in; (void)out_size;
    const float* x = (const float*)d_in[0];   // [65536, 512]
    const float* w = (const float*)d_in[1];   // [2000, 512]
    float* out = (float*)d_out;                           // [65536, 512]
    float* att = (float*)d_out + (size_t)NROWS * KDIM;    // [65536, 2000]

    k_gemm_exp<<<dim3(NMBLK, NROWS / BM), 256>>>(x, w);
    k_finish<<<NROWS / 8, 256>>>(w, out, att);
}

// round 5
// speedup vs baseline: 1.1121x; 1.1121x over previous
#include <cuda_runtime.h>
#include <cstdint>

#define FULL_MASK 0xffffffffu

static constexpr int NROWS = 65536;
static constexpr int KDIM  = 512;
static constexpr int MEM   = 2000;
static constexpr int MPAD  = 2048;
static constexpr float LAMBDA = 0.0025f;

// GEMM tiling
static constexpr int BM = 128;
static constexpr int BN = 128;
static constexpr int BK = 32;             // gmem k per chunk
static constexpr int NCHUNK = KDIM / BK;  // 16
static constexpr int NMBLK = MPAD / BN;   // 16 column blocks

// SMEM stage layout: 4 planes (Ah, Al, Bh, Bl), each 128 rows x 32 f32 = 16 KB
static constexpr int PLANE_BYTES = 128 * 32 * 4;       // 16384
static constexpr int STAGE_BYTES = 4 * PLANE_BYTES;    // 65536
static constexpr int SMEM_TOTAL  = 2 * STAGE_BYTES;    // 131072

// Scratch
__device__ __align__(128) float g_xhi[(size_t)NROWS * KDIM];
__device__ __align__(128) float g_xlo[(size_t)NROWS * KDIM];
__device__ __align__(128) float g_whi[(size_t)MPAD * KDIM];
__device__ __align__(128) float g_wlo[(size_t)MPAD * KDIM];
__device__ __align__(128) float g_E[(size_t)NROWS * MPAD];
__device__ float g_Zp[NMBLK * NROWS];

// ---------------- helpers ----------------
__device__ __forceinline__ uint32_t smem_u32(const void* p) {
    uint32_t a;
    asm("{ .reg .u64 t; cvta.to.shared.u64 t, %1; cvt.u32.u64 %0, t; }"
        : "=r"(a) : "l"(p));
    return a;
}
__device__ __forceinline__ void cpa16(uint32_t dst, const void* src) {
    asm volatile("cp.async.cg.shared.global [%0], [%1], 16;"
                 :: "r"(dst), "l"(src));
}
__device__ __forceinline__ void cpa_commit() {
    asm volatile("cp.async.commit_group;" ::: "memory");
}
template <int N>
__device__ __forceinline__ void cpa_wait() {
    asm volatile("cp.async.wait_group %0;" :: "n"(N) : "memory");
}
__device__ __forceinline__ float tf32_rn(float a) {
    uint32_t r;
    asm("cvt.rna.tf32.f32 %0, %1;" : "=r"(r) : "f"(a));
    return __uint_as_float(r);
}
__device__ __forceinline__ uint32_t swz128(uint32_t off) {
    return off ^ ((off >> 3) & 0x70);
}
__device__ __forceinline__ void ldsm4(uint32_t* r, uint32_t addr) {
    asm volatile("ldmatrix.sync.aligned.m8n8.x4.shared.b16 {%0,%1,%2,%3}, [%4];"
                 : "=r"(r[0]), "=r"(r[1]), "=r"(r[2]), "=r"(r[3]) : "r"(addr));
}
__device__ __forceinline__ void mma_tf32(float* c, const uint32_t* a,
                                         const uint32_t* b) {
    asm volatile(
        "mma.sync.aligned.m16n8k8.row.col.f32.tf32.tf32.f32 "
        "{%0,%1,%2,%3}, {%4,%5,%6,%7}, {%8,%9}, {%0,%1,%2,%3};"
        : "+f"(c[0]), "+f"(c[1]), "+f"(c[2]), "+f"(c[3])
        : "r"(a[0]), "r"(a[1]), "r"(a[2]), "r"(a[3]), "r"(b[0]), "r"(b[1]));
}

// ---------------------------------------------------------------------------
// K0a: split x into tf32 hi/lo
// ---------------------------------------------------------------------------
__global__ void __launch_bounds__(256)
k_prep_x(const float* __restrict__ x) {
    const size_t i = (size_t)blockIdx.x * 256 + threadIdx.x;
    float4 v = ((const float4*)x)[i];
    float4 hi, lo;
    hi.x = tf32_rn(v.x); lo.x = tf32_rn(v.x - hi.x);
    hi.y = tf32_rn(v.y); lo.y = tf32_rn(v.y - hi.y);
    hi.z = tf32_rn(v.z); lo.z = tf32_rn(v.z - hi.z);
    hi.w = tf32_rn(v.w); lo.w = tf32_rn(v.w - hi.w);
    ((float4*)g_xhi)[i] = hi;
    ((float4*)g_xlo)[i] = lo;
}

// ---------------------------------------------------------------------------
// K0b: split W into tf32 hi/lo, zero-pad rows [2000, 2048)
// ---------------------------------------------------------------------------
__global__ void __launch_bounds__(256)
k_prep_w(const float* __restrict__ w) {
    const size_t i = (size_t)blockIdx.x * 256 + threadIdx.x;
    const int row = (int)(i / (KDIM / 4));
    float4 hi = make_float4(0.f, 0.f, 0.f, 0.f);
    float4 lo = make_float4(0.f, 0.f, 0.f, 0.f);
    if (row < MEM) {
        float4 v = ((const float4*)w)[i];
        hi.x = tf32_rn(v.x); lo.x = tf32_rn(v.x - hi.x);
        hi.y = tf32_rn(v.y); lo.y = tf32_rn(v.y - hi.y);
        hi.z = tf32_rn(v.z); lo.z = tf32_rn(v.z - hi.z);
        hi.w = tf32_rn(v.w); lo.w = tf32_rn(v.w - hi.w);
    }
    ((float4*)g_whi)[i] = hi;
    ((float4*)g_wlo)[i] = lo;
}

// ---------------------------------------------------------------------------
// K1: 3xTF32 mma.sync GEMM (HMMA), fused exp epilogue
//   logits[128x128] = xhi*whi^T + xhi*wlo^T + xlo*whi^T (fp32 accum in regs)
//   E = exp(logit) -> g_E ; per-colblock row sums -> g_Zp
// Addressing rule: keep UNSWIZZLED offsets, XOR the per-thread row mask LAST
// (post-swizzle adds can carry out of bits[6:4] into the row field -> OOB).
// ---------------------------------------------------------------------------
__global__ void __launch_bounds__(256, 1)
k_gemm_mma() {
    extern __shared__ __align__(1024) char smem[];
    const uint32_t sb = smem_u32(smem);
    const int tid  = threadIdx.x;
    const int lane = tid & 31;
    const int wrp  = tid >> 5;
    const int warp_m = wrp >> 2;          // 0..1  (64 rows each)
    const int warp_n = wrp & 3;           // 0..3  (32 cols each)
    const int row0 = blockIdx.y * BM;
    const int col0 = blockIdx.x * BN;

    // ldmatrix per-thread UNSWIZZLED base offsets + row masks (XOR-last)
    const int a_row = warp_m * 64 + (lane & 7) + ((lane >> 3) & 1) * 8;
    const uint32_t a_base = (uint32_t)(a_row * 128 + ((lane >> 4) & 1) * 16);
    const uint32_t a_mask = (uint32_t)((a_row & 7) << 4);
    const int b_row = warp_n * 32 + ((lane >> 4) & 1) * 8 + (lane & 7);
    const uint32_t b_base = (uint32_t)(b_row * 128 + ((lane >> 3) & 1) * 16);
    const uint32_t b_mask = (uint32_t)((b_row & 7) << 4);

    float acc[4][4][4];
    #pragma unroll
    for (int mt = 0; mt < 4; mt++)
        #pragma unroll
        for (int nt = 0; nt < 4; nt++)
            #pragma unroll
            for (int q = 0; q < 4; q++) acc[mt][nt][q] = 0.f;

    auto load_chunk = [&](int ch, int buf) {
        const uint32_t stage = sb + buf * STAGE_BYTES;
        const int k0 = ch * BK;
        #pragma unroll
        for (int j = 0; j < 4; j++) {
            const int u = tid * 4 + j;
            const int r = u >> 3;
            const int g = u & 7;
            const uint32_t d = swz128((uint32_t)(r * 128 + g * 16));
            const size_t offA = ((size_t)(row0 + r) * KDIM + k0) * 4 + g * 16;
            const size_t offB = ((size_t)(col0 + r) * KDIM + k0) * 4 + g * 16;
            cpa16(stage + d,                   (const char*)g_xhi + offA);
            cpa16(stage + PLANE_BYTES + d,     (const char*)g_xlo + offA);
            cpa16(stage + 2 * PLANE_BYTES + d, (const char*)g_whi + offB);
            cpa16(stage + 3 * PLANE_BYTES + d, (const char*)g_wlo + offB);
        }
    };

    load_chunk(0, 0);
    cpa_commit();

    for (int ch = 0; ch < NCHUNK; ch++) {
        const int buf = ch & 1;
        if (ch < NCHUNK - 1) {
            load_chunk(ch + 1, buf ^ 1);
            cpa_commit();
            cpa_wait<1>();
        } else {
            cpa_wait<0>();
        }
        __syncthreads();

        const uint32_t st = sb + buf * STAGE_BYTES;
        #pragma unroll
        for (int ks = 0; ks < 4; ks++) {
            uint32_t Ah[4][4], Al[4][4];
            #pragma unroll
            for (int mt = 0; mt < 4; mt++) {
                const uint32_t au =
                    (a_base + (uint32_t)(mt * 2048 + ks * 32)) ^ a_mask;
                ldsm4(Ah[mt], st + au);
                ldsm4(Al[mt], st + PLANE_BYTES + au);
            }
            uint32_t Bh[4][2], Bl[4][2];
            #pragma unroll
            for (int pr = 0; pr < 2; pr++) {
                const uint32_t bu =
                    (b_base + (uint32_t)(pr * 2048 + ks * 32)) ^ b_mask;
                uint32_t r4[4];
                ldsm4(r4, st + 2 * PLANE_BYTES + bu);
                Bh[pr * 2][0] = r4[0]; Bh[pr * 2][1] = r4[1];
                Bh[pr * 2 + 1][0] = r4[2]; Bh[pr * 2 + 1][1] = r4[3];
                ldsm4(r4, st + 3 * PLANE_BYTES + bu);
                Bl[pr * 2][0] = r4[0]; Bl[pr * 2][1] = r4[1];
                Bl[pr * 2 + 1][0] = r4[2]; Bl[pr * 2 + 1][1] = r4[3];
            }
            #pragma unroll
            for (int mt = 0; mt < 4; mt++)
                #pragma unroll
                for (int nt = 0; nt < 4; nt++) {
                    mma_tf32(acc[mt][nt], Ah[mt], Bh[nt]);
                    mma_tf32(acc[mt][nt], Ah[mt], Bl[nt]);
                    mma_tf32(acc[mt][nt], Al[mt], Bh[nt]);
                }
        }
        __syncthreads();
    }

    // ---- epilogue: exp, mask, store E, per-row sums ----
    float* srows = (float*)smem;   // [128][4] partial sums
    float rsl[4], rsh[4];
    #pragma unroll
    for (int mt = 0; mt < 4; mt++) { rsl[mt] = 0.f; rsh[mt] = 0.f; }

    #pragma unroll
    for (int mt = 0; mt < 4; mt++) {
        const int rl = warp_m * 64 + mt * 16 + (lane >> 2);
        #pragma unroll
        for (int nt = 0; nt < 4; nt++) {
            const int gc = col0 + warp_n * 32 + nt * 8 + (lane & 3) * 2;
            float e0 = expf(acc[mt][nt][0]);
            float e1 = expf(acc[mt][nt][1]);
            float e2 = expf(acc[mt][nt][2]);
            float e3 = expf(acc[mt][nt][3]);
            if (gc >= MEM)     { e0 = 0.f; e2 = 0.f; }
            if (gc + 1 >= MEM) { e1 = 0.f; e3 = 0.f; }
            const int growl = row0 + rl;
            *(float2*)(g_E + (size_t)growl * MPAD + gc) = make_float2(e0, e1);
            *(float2*)(g_E + (size_t)(growl + 8) * MPAD + gc) = make_float2(e2, e3);
            rsl[mt] += e0 + e1;
            rsh[mt] += e2 + e3;
        }
    }
    #pragma unroll
    for (int mt = 0; mt < 4; mt++) {
        #pragma unroll
        for (int o = 1; o <= 2; o <<= 1) {
            rsl[mt] += __shfl_xor_sync(FULL_MASK, rsl[mt], o);
            rsh[mt] += __shfl_xor_sync(FULL_MASK, rsh[mt], o);
        }
    }
    if ((lane & 3) == 0) {
        #pragma unroll
        for (int mt = 0; mt < 4; mt++) {
            const int rl = warp_m * 64 + mt * 16 + (lane >> 2);
            srows[rl * 4 + warp_n] = rsl[mt];
            srows[(rl + 8) * 4 + warp_n] = rsh[mt];
        }
    }
    __syncthreads();
    if (tid < 128) {
        const float z = srows[tid * 4 + 0] + srows[tid * 4 + 1] +
                        srows[tid * 4 + 2] + srows[tid * 4 + 3];
        g_Zp[blockIdx.x * NROWS + row0 + tid] = z;
    }
}

// ---------------------------------------------------------------------------
// K2: per row (1 warp/row): Z, threshold, survivor sum, att write, sparse out
// ---------------------------------------------------------------------------
__global__ void __launch_bounds__(256)
k_finish(const float* __restrict__ w, float* __restrict__ out,
         float* __restrict__ att) {
    const int lane = threadIdx.x & 31;
    const int wid  = threadIdx.x >> 5;
    const int n    = blockIdx.x * 8 + wid;

    const float4* E4 = (const float4*)(g_E + (size_t)n * MPAD);

    float Z = 0.f;
    #pragma unroll
    for (int j = 0; j < NMBLK; j++) Z += g_Zp[j * NROWS + n];
    const float t = LAMBDA * Z;

    float s = 0.f;
    for (int i = lane; i < MEM / 4; i += 32) {
        float4 v = E4[i];
        if (v.x > t) s += v.x;
        if (v.y > t) s += v.y;
        if (v.z > t) s += v.z;
        if (v.w > t) s += v.w;
    }
    #pragma unroll
    for (int o = 16; o; o >>= 1) s += __shfl_xor_sync(FULL_MASK, s, o);
    const float inv = (s > 0.f) ? (1.0f / s) : 0.f;

    float4* att4 = (float4*)(att + (size_t)n * MEM);
    float oacc[16];
    #pragma unroll
    for (int q = 0; q < 16; q++) oacc[q] = 0.f;

    for (int it = 0; it < 16; it++) {
        const int i = lane + 32 * it;
        const bool active = (i < MEM / 4);
        float4 v = active ? E4[i] : make_float4(0.f, 0.f, 0.f, 0.f);
        float4 o;
        int m4 = 0;
        o.x = (v.x > t) ? v.x * inv : 0.f; if (v.x > t) m4 |= 1;
        o.y = (v.y > t) ? v.y * inv : 0.f; if (v.y > t) m4 |= 2;
        o.z = (v.z > t) ? v.z * inv : 0.f; if (v.z > t) m4 |= 4;
        o.w = (v.w > t) ? v.w * inv : 0.f; if (v.w > t) m4 |= 8;
        if (active) att4[i] = o;

        unsigned bal = __ballot_sync(FULL_MASK, m4 != 0);
        while (bal) {
            const int src = __ffs(bal) - 1;
            bal &= bal - 1;
            const int sm4 = __shfl_sync(FULL_MASK, m4, src);
            float av[4];
            av[0] = __shfl_sync(FULL_MASK, o.x, src);
            av[1] = __shfl_sync(FULL_MASK, o.y, src);
            av[2] = __shfl_sync(FULL_MASK, o.z, src);
            av[3] = __shfl_sync(FULL_MASK, o.w, src);
            const int mbase = 4 * (src + 32 * it);
            #pragma unroll
            for (int j = 0; j < 4; j++) {
                if (sm4 & (1 << j)) {
                    const float* wr = w + (size_t)(mbase + j) * KDIM;
                    const float a = av[j];
                    #pragma unroll
                    for (int q = 0; q < 16; q++)
                        oacc[q] += a * wr[lane + 32 * q];
                }
            }
        }
    }

    float* orow = out + (size_t)n * KDIM;
    #pragma unroll
    for (int q = 0; q < 16; q++) orow[lane + 32 * q] = oacc[q];
}

// ---------------------------------------------------------------------------
extern "C" void kernel_launch(void* const* d_in, const int* in_sizes, int n_in,
                              void* d_out, int out_size) {
    (void)in_sizes; (void)n_in; (void)out_size;
    const float* x = (const float*)d_in[0];
    const float* w = (const float*)d_in[1];
    float* out = (float*)d_out;
    float* att = (float*)d_out + (size_t)NROWS * KDIM;

    cudaFuncSetAttribute(k_gemm_mma,
                         cudaFuncAttributeMaxDynamicSharedMemorySize, SMEM_TOTAL);

    k_prep_x<<<(NROWS * KDIM / 4) / 256, 256>>>(x);
    k_prep_w<<<(MPAD * KDIM / 4) / 256, 256>>>(w);
    k_gemm_mma<<<dim3(MPAD / BN, NROWS / BM), 256, SMEM_TOTAL>>>();
    k_finish<<<NROWS / 8, 256>>>(w, out, att);
}

// round 6
// speedup vs baseline: 1.9248x; 1.7308x over previous
#include <cuda_runtime.h>
#include <cuda_fp16.h>
#include <cstdint>

#define FULL_MASK 0xffffffffu

static constexpr int NROWS = 65536;
static constexpr int KDIM  = 512;
static constexpr int MEM   = 2000;
static constexpr int MPAD  = 2048;
static constexpr float LAMBDA = 0.0025f;
static constexpr float LO_SCALE = 2048.0f;       // 2^11
static constexpr float LO_INV   = 1.0f / 2048.0f;

// GEMM tiling
static constexpr int BM = 128;
static constexpr int BN = 128;
static constexpr int BK = 64;             // k elems per chunk (128 B fp16 rows)
static constexpr int NCHUNK = KDIM / BK;  // 8
static constexpr int NMBLK = MPAD / BN;   // 16 column blocks

// SMEM: 4 planes (Ah, Al, Bh, Bl), each 128 rows x 64 fp16 = 16 KB
static constexpr int PLANE_BYTES = 128 * 64 * 2;       // 16384
static constexpr int STAGE_BYTES = 4 * PLANE_BYTES;    // 65536
static constexpr int SMEM_TOTAL  = 2 * STAGE_BYTES;    // 131072

// Scratch (fp16 hi / scaled-lo planes)
__device__ __align__(128) __half g_xhi[(size_t)NROWS * KDIM];
__device__ __align__(128) __half g_xlo[(size_t)NROWS * KDIM];   // 2048*(x-hi)
__device__ __align__(128) __half g_whi[(size_t)MPAD * KDIM];
__device__ __align__(128) __half g_wlo[(size_t)MPAD * KDIM];    // 2048*(w-hi)
__device__ __align__(128) float g_E[(size_t)NROWS * MPAD];
__device__ float g_Zp[NMBLK * NROWS];

// ---------------- helpers ----------------
__device__ __forceinline__ uint32_t smem_u32(const void* p) {
    uint32_t a;
    asm("{ .reg .u64 t; cvta.to.shared.u64 t, %1; cvt.u32.u64 %0, t; }"
        : "=r"(a) : "l"(p));
    return a;
}
__device__ __forceinline__ void cpa16(uint32_t dst, const void* src) {
    asm volatile("cp.async.cg.shared.global [%0], [%1], 16;"
                 :: "r"(dst), "l"(src));
}
__device__ __forceinline__ void cpa_commit() {
    asm volatile("cp.async.commit_group;" ::: "memory");
}
template <int N>
__device__ __forceinline__ void cpa_wait() {
    asm volatile("cp.async.wait_group %0;" :: "n"(N) : "memory");
}
__device__ __forceinline__ uint32_t swz128(uint32_t off) {
    return off ^ ((off >> 3) & 0x70);
}
__device__ __forceinline__ void ldsm4(uint32_t* r, uint32_t addr) {
    asm volatile("ldmatrix.sync.aligned.m8n8.x4.shared.b16 {%0,%1,%2,%3}, [%4];"
                 : "=r"(r[0]), "=r"(r[1]), "=r"(r[2]), "=r"(r[3]) : "r"(addr));
}
__device__ __forceinline__ void mma_f16(float* c, const uint32_t* a,
                                        const uint32_t* b) {
    asm volatile(
        "mma.sync.aligned.m16n8k16.row.col.f32.f16.f16.f32 "
        "{%0,%1,%2,%3}, {%4,%5,%6,%7}, {%8,%9}, {%0,%1,%2,%3};"
        : "+f"(c[0]), "+f"(c[1]), "+f"(c[2]), "+f"(c[3])
        : "r"(a[0]), "r"(a[1]), "r"(a[2]), "r"(a[3]), "r"(b[0]), "r"(b[1]));
}

// ---------------------------------------------------------------------------
// K0a: split x into fp16 hi + scaled lo
// ---------------------------------------------------------------------------
__global__ void __launch_bounds__(256)
k_prep_x(const float* __restrict__ x) {
    const size_t i = (size_t)blockIdx.x * 256 + threadIdx.x;
    float4 v = ((const float4*)x)[i];
    __half h0 = __float2half_rn(v.x), h1 = __float2half_rn(v.y);
    __half h2 = __float2half_rn(v.z), h3 = __float2half_rn(v.w);
    __half l0 = __float2half_rn((v.x - __half2float(h0)) * LO_SCALE);
    __half l1 = __float2half_rn((v.y - __half2float(h1)) * LO_SCALE);
    __half l2 = __float2half_rn((v.z - __half2float(h2)) * LO_SCALE);
    __half l3 = __float2half_rn((v.w - __half2float(h3)) * LO_SCALE);
    ((__half2*)g_xhi)[i * 2]     = __halves2half2(h0, h1);
    ((__half2*)g_xhi)[i * 2 + 1] = __halves2half2(h2, h3);
    ((__half2*)g_xlo)[i * 2]     = __halves2half2(l0, l1);
    ((__half2*)g_xlo)[i * 2 + 1] = __halves2half2(l2, l3);
}

// ---------------------------------------------------------------------------
// K0b: split W, zero-pad rows [2000, 2048)
// ---------------------------------------------------------------------------
__global__ void __launch_bounds__(256)
k_prep_w(const float* __restrict__ w) {
    const size_t i = (size_t)blockIdx.x * 256 + threadIdx.x;
    const int row = (int)(i / (KDIM / 4));
    float4 v = make_float4(0.f, 0.f, 0.f, 0.f);
    if (row < MEM) v = ((const float4*)w)[i];
    __half h0 = __float2half_rn(v.x), h1 = __float2half_rn(v.y);
    __half h2 = __float2half_rn(v.z), h3 = __float2half_rn(v.w);
    __half l0 = __float2half_rn((v.x - __half2float(h0)) * LO_SCALE);
    __half l1 = __float2half_rn((v.y - __half2float(h1)) * LO_SCALE);
    __half l2 = __float2half_rn((v.z - __half2float(h2)) * LO_SCALE);
    __half l3 = __float2half_rn((v.w - __half2float(h3)) * LO_SCALE);
    ((__half2*)g_whi)[i * 2]     = __halves2half2(h0, h1);
    ((__half2*)g_whi)[i * 2 + 1] = __halves2half2(h2, h3);
    ((__half2*)g_wlo)[i * 2]     = __halves2half2(l0, l1);
    ((__half2*)g_wlo)[i * 2 + 1] = __halves2half2(l2, l3);
}

// ---------------------------------------------------------------------------
// K1: 3xFP16 mma.sync GEMM (m16n8k16), fused exp epilogue
//   acc_main = xh*wh^T ; acc_corr = xh*wl'^T + xl'*wh^T  (both scaled 2048)
//   logit = acc_main + acc_corr/2048 ; E=exp -> g_E ; row sums -> g_Zp
// XOR-last swizzle addressing throughout.
// ---------------------------------------------------------------------------
__global__ void __launch_bounds__(256, 1)
k_gemm_mma() {
    extern __shared__ __align__(1024) char smem[];
    const uint32_t sb = smem_u32(smem);
    const int tid  = threadIdx.x;
    const int lane = tid & 31;
    const int wrp  = tid >> 5;
    const int warp_m = wrp >> 2;          // 0..1 (64 rows)
    const int warp_n = wrp & 3;           // 0..3 (32 cols)
    const int row0 = blockIdx.y * BM;
    const int col0 = blockIdx.x * BN;

    // A: lane -> row warp_m*64 + (lane&15), k-half (lane>>4)
    const int a_row = warp_m * 64 + (lane & 15);
    const uint32_t a_base = (uint32_t)(a_row * 128 + ((lane >> 4) & 1) * 16);
    const uint32_t a_mask = (uint32_t)((a_row & 7) << 4);
    // B: lane -> n-row warp_n*32 + (lane&7) + ((lane>>4)&1)*8, k-half ((lane>>3)&1)
    const int b_row = warp_n * 32 + (lane & 7) + ((lane >> 4) & 1) * 8;
    const uint32_t b_base = (uint32_t)(b_row * 128 + ((lane >> 3) & 1) * 16);
    const uint32_t b_mask = (uint32_t)((b_row & 7) << 4);

    float am[4][4][4];   // main accumulators
    float ac[4][4][4];   // correction accumulators (scale 2048)
    #pragma unroll
    for (int mt = 0; mt < 4; mt++)
        #pragma unroll
        for (int nt = 0; nt < 4; nt++)
            #pragma unroll
            for (int q = 0; q < 4; q++) { am[mt][nt][q] = 0.f; ac[mt][nt][q] = 0.f; }

    auto load_chunk = [&](int ch, int buf) {
        const uint32_t stage = sb + buf * STAGE_BYTES;
        const int k0 = ch * BK;
        #pragma unroll
        for (int j = 0; j < 4; j++) {
            const int u = tid * 4 + j;
            const int r = u >> 3;          // 0..127
            const int g = u & 7;           // 16B group within 128B row
            const uint32_t d = swz128((uint32_t)(r * 128 + g * 16));
            const size_t offA = ((size_t)(row0 + r) * KDIM + k0 + g * 8) * 2;
            const size_t offB = ((size_t)(col0 + r) * KDIM + k0 + g * 8) * 2;
            cpa16(stage + d,                   (const char*)g_xhi + offA);
            cpa16(stage + PLANE_BYTES + d,     (const char*)g_xlo + offA);
            cpa16(stage + 2 * PLANE_BYTES + d, (const char*)g_whi + offB);
            cpa16(stage + 3 * PLANE_BYTES + d, (const char*)g_wlo + offB);
        }
    };

    load_chunk(0, 0);
    cpa_commit();

    for (int ch = 0; ch < NCHUNK; ch++) {
        const int buf = ch & 1;
        if (ch < NCHUNK - 1) {
            load_chunk(ch + 1, buf ^ 1);
            cpa_commit();
            cpa_wait<1>();
        } else {
            cpa_wait<0>();
        }
        __syncthreads();

        const uint32_t st = sb + buf * STAGE_BYTES;
        #pragma unroll
        for (int ks = 0; ks < 4; ks++) {           // k = 16 per step
            uint32_t Ah[4][4], Al[4][4];
            #pragma unroll
            for (int mt = 0; mt < 4; mt++) {
                const uint32_t au =
                    (a_base + (uint32_t)(mt * 2048 + ks * 32)) ^ a_mask;
                ldsm4(Ah[mt], st + au);
                ldsm4(Al[mt], st + PLANE_BYTES + au);
            }
            uint32_t Bh[4][2], Bl[4][2];
            #pragma unroll
            for (int pr = 0; pr < 2; pr++) {       // nt pairs {0,1},{2,3}
                const uint32_t bu =
                    (b_base + (uint32_t)(pr * 2048 + ks * 32)) ^ b_mask;
                uint32_t r4[4];
                ldsm4(r4, st + 2 * PLANE_BYTES + bu);
                Bh[pr * 2][0] = r4[0]; Bh[pr * 2][1] = r4[1];
                Bh[pr * 2 + 1][0] = r4[2]; Bh[pr * 2 + 1][1] = r4[3];
                ldsm4(r4, st + 3 * PLANE_BYTES + bu);
                Bl[pr * 2][0] = r4[0]; Bl[pr * 2][1] = r4[1];
                Bl[pr * 2 + 1][0] = r4[2]; Bl[pr * 2 + 1][1] = r4[3];
            }
            #pragma unroll
            for (int mt = 0; mt < 4; mt++)
                #pragma unroll
                for (int nt = 0; nt < 4; nt++) {
                    mma_f16(am[mt][nt], Ah[mt], Bh[nt]);
                    mma_f16(ac[mt][nt], Ah[mt], Bl[nt]);
                    mma_f16(ac[mt][nt], Al[mt], Bh[nt]);
                }
        }
        __syncthreads();
    }

    // ---- epilogue: combine, exp, mask, store E, per-row sums ----
    float* srows = (float*)smem;   // [128][4] partial sums
    float rsl[4], rsh[4];
    #pragma unroll
    for (int mt = 0; mt < 4; mt++) { rsl[mt] = 0.f; rsh[mt] = 0.f; }

    #pragma unroll
    for (int mt = 0; mt < 4; mt++) {
        const int rl = warp_m * 64 + mt * 16 + (lane >> 2);
        #pragma unroll
        for (int nt = 0; nt < 4; nt++) {
            const int gc = col0 + warp_n * 32 + nt * 8 + (lane & 3) * 2;
            float e0 = expf(am[mt][nt][0] + ac[mt][nt][0] * LO_INV);
            float e1 = expf(am[mt][nt][1] + ac[mt][nt][1] * LO_INV);
            float e2 = expf(am[mt][nt][2] + ac[mt][nt][2] * LO_INV);
            float e3 = expf(am[mt][nt][3] + ac[mt][nt][3] * LO_INV);
            if (gc >= MEM)     { e0 = 0.f; e2 = 0.f; }
            if (gc + 1 >= MEM) { e1 = 0.f; e3 = 0.f; }
            const int growl = row0 + rl;
            *(float2*)(g_E + (size_t)growl * MPAD + gc) = make_float2(e0, e1);
            *(float2*)(g_E + (size_t)(growl + 8) * MPAD + gc) = make_float2(e2, e3);
            rsl[mt] += e0 + e1;
            rsh[mt] += e2 + e3;
        }
    }
    #pragma unroll
    for (int mt = 0; mt < 4; mt++) {
        #pragma unroll
        for (int o = 1; o <= 2; o <<= 1) {
            rsl[mt] += __shfl_xor_sync(FULL_MASK, rsl[mt], o);
            rsh[mt] += __shfl_xor_sync(FULL_MASK, rsh[mt], o);
        }
    }
    if ((lane & 3) == 0) {
        #pragma unroll
        for (int mt = 0; mt < 4; mt++) {
            const int rl = warp_m * 64 + mt * 16 + (lane >> 2);
            srows[rl * 4 + warp_n] = rsl[mt];
            srows[(rl + 8) * 4 + warp_n] = rsh[mt];
        }
    }
    __syncthreads();
    if (tid < 128) {
        const float z = srows[tid * 4 + 0] + srows[tid * 4 + 1] +
                        srows[tid * 4 + 2] + srows[tid * 4 + 3];
        g_Zp[blockIdx.x * NROWS + row0 + tid] = z;
    }
}

// ---------------------------------------------------------------------------
// K2: per row (1 warp/row): Z, threshold, survivor sum, att write, sparse out
// ---------------------------------------------------------------------------
__global__ void __launch_bounds__(256)
k_finish(const float* __restrict__ w, float* __restrict__ out,
         float* __restrict__ att) {
    const int lane = threadIdx.x & 31;
    const int wid  = threadIdx.x >> 5;
    const int n    = blockIdx.x * 8 + wid;

    const float4* E4 = (const float4*)(g_E + (size_t)n * MPAD);

    float Z = 0.f;
    #pragma unroll
    for (int j = 0; j < NMBLK; j++) Z += g_Zp[j * NROWS + n];
    const float t = LAMBDA * Z;

    float s = 0.f;
    for (int i = lane; i < MEM / 4; i += 32) {
        float4 v = E4[i];
        if (v.x > t) s += v.x;
        if (v.y > t) s += v.y;
        if (v.z > t) s += v.z;
        if (v.w > t) s += v.w;
    }
    #pragma unroll
    for (int o = 16; o; o >>= 1) s += __shfl_xor_sync(FULL_MASK, s, o);
    const float inv = (s > 0.f) ? (1.0f / s) : 0.f;

    float4* att4 = (float4*)(att + (size_t)n * MEM);
    float oacc[16];
    #pragma unroll
    for (int q = 0; q < 16; q++) oacc[q] = 0.f;

    for (int it = 0; it < 16; it++) {
        const int i = lane + 32 * it;
        const bool active = (i < MEM / 4);
        float4 v = active ? E4[i] : make_float4(0.f, 0.f, 0.f, 0.f);
        float4 o;
        int m4 = 0;
        o.x = (v.x > t) ? v.x * inv : 0.f; if (v.x > t) m4 |= 1;
        o.y = (v.y > t) ? v.y * inv : 0.f; if (v.y > t) m4 |= 2;
        o.z = (v.z > t) ? v.z * inv : 0.f; if (v.z > t) m4 |= 4;
        o.w = (v.w > t) ? v.w * inv : 0.f; if (v.w > t) m4 |= 8;
        if (active) att4[i] = o;

        unsigned bal = __ballot_sync(FULL_MASK, m4 != 0);
        while (bal) {
            const int src = __ffs(bal) - 1;
            bal &= bal - 1;
            const int sm4 = __shfl_sync(FULL_MASK, m4, src);
            float av[4];
            av[0] = __shfl_sync(FULL_MASK, o.x, src);
            av[1] = __shfl_sync(FULL_MASK, o.y, src);
            av[2] = __shfl_sync(FULL_MASK, o.z, src);
            av[3] = __shfl_sync(FULL_MASK, o.w, src);
            const int mbase = 4 * (src + 32 * it);
            #pragma unroll
            for (int j = 0; j < 4; j++) {
                if (sm4 & (1 << j)) {
                    const float* wr = w + (size_t)(mbase + j) * KDIM;
                    const float a = av[j];
                    #pragma unroll
                    for (int q = 0; q < 16; q++)
                        oacc[q] += a * wr[lane + 32 * q];
                }
            }
        }
    }

    float* orow = out + (size_t)n * KDIM;
    #pragma unroll
    for (int q = 0; q < 16; q++) orow[lane + 32 * q] = oacc[q];
}

// ---------------------------------------------------------------------------
extern "C" void kernel_launch(void* const* d_in, const int* in_sizes, int n_in,
                              void* d_out, int out_size) {
    (void)in_sizes; (void)n_in; (void)out_size;
    const float* x = (const float*)d_in[0];
    const float* w = (const float*)d_in[1];
    float* out = (float*)d_out;
    float* att = (float*)d_out + (size_t)NROWS * KDIM;

    cudaFuncSetAttribute(k_gemm_mma,
                         cudaFuncAttributeMaxDynamicSharedMemorySize, SMEM_TOTAL);

    k_prep_x<<<(NROWS * KDIM / 4) / 256, 256>>>(x);
    k_prep_w<<<(MPAD * KDIM / 4) / 256, 256>>>(w);
    k_gemm_mma<<<dim3(MPAD / BN, NROWS / BM), 256, SMEM_TOTAL>>>();
    k_finish<<<NROWS / 8, 256>>>(w, out, att);
}

// round 7
// speedup vs baseline: 2.2176x; 1.1521x over previous
#include <cuda_runtime.h>
#include <cuda_fp16.h>
#include <cstdint>

#define FULL_MASK 0xffffffffu

static constexpr int NROWS = 65536;
static constexpr int KDIM  = 512;
static constexpr int MEM   = 2000;
static constexpr int MPAD  = 2048;
static constexpr float LAMBDA = 0.0025f;
static constexpr float LO_SCALE = 2048.0f;       // 2^11
static constexpr float LO_INV   = 1.0f / 2048.0f;

// GEMM tiling
static constexpr int BM = 128;
static constexpr int BN = 128;
static constexpr int BK = 64;             // k elems per chunk (128 B fp16 rows)
static constexpr int NCHUNK = KDIM / BK;  // 8
static constexpr int NMBLK = MPAD / BN;   // 16 column blocks
static constexpr int NSTAGE = 3;

// SMEM: per stage 4 planes (Ah, Al, Bh, Bl), each 128 rows x 64 fp16 = 16 KB
static constexpr int PLANE_BYTES = 128 * 64 * 2;       // 16384
static constexpr int STAGE_BYTES = 4 * PLANE_BYTES;    // 65536
static constexpr int SMEM_TOTAL  = NSTAGE * STAGE_BYTES;  // 196608

// Scratch (fp16 hi / scaled-lo planes)
__device__ __align__(128) __half g_xhi[(size_t)NROWS * KDIM];
__device__ __align__(128) __half g_xlo[(size_t)NROWS * KDIM];   // 2048*(x-hi)
__device__ __align__(128) __half g_whi[(size_t)MPAD * KDIM];
__device__ __align__(128) __half g_wlo[(size_t)MPAD * KDIM];    // 2048*(w-hi)
__device__ __align__(128) float g_E[(size_t)NROWS * MPAD];
__device__ float g_Zp[NMBLK * NROWS];

// ---------------- helpers ----------------
__device__ __forceinline__ uint32_t smem_u32(const void* p) {
    uint32_t a;
    asm("{ .reg .u64 t; cvta.to.shared.u64 t, %1; cvt.u32.u64 %0, t; }"
        : "=r"(a) : "l"(p));
    return a;
}
__device__ __forceinline__ void cpa16(uint32_t dst, const void* src) {
    asm volatile("cp.async.cg.shared.global [%0], [%1], 16;"
                 :: "r"(dst), "l"(src));
}
__device__ __forceinline__ void cpa_commit() {
    asm volatile("cp.async.commit_group;" ::: "memory");
}
template <int N>
__device__ __forceinline__ void cpa_wait() {
    asm volatile("cp.async.wait_group %0;" :: "n"(N) : "memory");
}
__device__ __forceinline__ uint32_t swz128(uint32_t off) {
    return off ^ ((off >> 3) & 0x70);
}
__device__ __forceinline__ void ldsm4(uint32_t* r, uint32_t addr) {
    asm volatile("ldmatrix.sync.aligned.m8n8.x4.shared.b16 {%0,%1,%2,%3}, [%4];"
                 : "=r"(r[0]), "=r"(r[1]), "=r"(r[2]), "=r"(r[3]) : "r"(addr));
}
__device__ __forceinline__ void mma_f16(float* c, const uint32_t* a,
                                        const uint32_t* b) {
    asm volatile(
        "mma.sync.aligned.m16n8k16.row.col.f32.f16.f16.f32 "
        "{%0,%1,%2,%3}, {%4,%5,%6,%7}, {%8,%9}, {%0,%1,%2,%3};"
        : "+f"(c[0]), "+f"(c[1]), "+f"(c[2]), "+f"(c[3])
        : "r"(a[0]), "r"(a[1]), "r"(a[2]), "r"(a[3]), "r"(b[0]), "r"(b[1]));
}

// ---------------------------------------------------------------------------
// K0a: split x into fp16 hi + scaled lo
// ---------------------------------------------------------------------------
__global__ void __launch_bounds__(256)
k_prep_x(const float* __restrict__ x) {
    const size_t i = (size_t)blockIdx.x * 256 + threadIdx.x;
    float4 v = ((const float4*)x)[i];
    __half h0 = __float2half_rn(v.x), h1 = __float2half_rn(v.y);
    __half h2 = __float2half_rn(v.z), h3 = __float2half_rn(v.w);
    __half l0 = __float2half_rn((v.x - __half2float(h0)) * LO_SCALE);
    __half l1 = __float2half_rn((v.y - __half2float(h1)) * LO_SCALE);
    __half l2 = __float2half_rn((v.z - __half2float(h2)) * LO_SCALE);
    __half l3 = __float2half_rn((v.w - __half2float(h3)) * LO_SCALE);
    ((__half2*)g_xhi)[i * 2]     = __halves2half2(h0, h1);
    ((__half2*)g_xhi)[i * 2 + 1] = __halves2half2(h2, h3);
    ((__half2*)g_xlo)[i * 2]     = __halves2half2(l0, l1);
    ((__half2*)g_xlo)[i * 2 + 1] = __halves2half2(l2, l3);
}

// ---------------------------------------------------------------------------
// K0b: split W, zero-pad rows [2000, 2048)
// ---------------------------------------------------------------------------
__global__ void __launch_bounds__(256)
k_prep_w(const float* __restrict__ w) {
    const size_t i = (size_t)blockIdx.x * 256 + threadIdx.x;
    const int row = (int)(i / (KDIM / 4));
    float4 v = make_float4(0.f, 0.f, 0.f, 0.f);
    if (row < MEM) v = ((const float4*)w)[i];
    __half h0 = __float2half_rn(v.x), h1 = __float2half_rn(v.y);
    __half h2 = __float2half_rn(v.z), h3 = __float2half_rn(v.w);
    __half l0 = __float2half_rn((v.x - __half2float(h0)) * LO_SCALE);
    __half l1 = __float2half_rn((v.y - __half2float(h1)) * LO_SCALE);
    __half l2 = __float2half_rn((v.z - __half2float(h2)) * LO_SCALE);
    __half l3 = __float2half_rn((v.w - __half2float(h3)) * LO_SCALE);
    ((__half2*)g_whi)[i * 2]     = __halves2half2(h0, h1);
    ((__half2*)g_whi)[i * 2 + 1] = __halves2half2(h2, h3);
    ((__half2*)g_wlo)[i * 2]     = __halves2half2(l0, l1);
    ((__half2*)g_wlo)[i * 2 + 1] = __halves2half2(l2, l3);
}

// ---------------------------------------------------------------------------
// K1: 3xFP16 mma.sync GEMM, 512 threads (16 warps, warp tile 32x32),
//     3-stage cp.async pipeline, fused exp epilogue.
// ---------------------------------------------------------------------------
__global__ void __launch_bounds__(512, 1)
k_gemm_mma() {
    extern __shared__ __align__(1024) char smem[];
    const uint32_t sb = smem_u32(smem);
    const int tid  = threadIdx.x;
    const int lane = tid & 31;
    const int wrp  = tid >> 5;
    const int warp_m = wrp >> 2;          // 0..3 (32 rows each)
    const int warp_n = wrp & 3;           // 0..3 (32 cols each)
    const int row0 = blockIdx.y * BM;
    const int col0 = blockIdx.x * BN;

    // ldmatrix unswizzled bases + XOR-last masks
    const int a_row = warp_m * 32 + (lane & 15);
    const uint32_t a_base = (uint32_t)(a_row * 128 + ((lane >> 4) & 1) * 16);
    const uint32_t a_mask = (uint32_t)((a_row & 7) << 4);
    const int b_row = warp_n * 32 + (lane & 7) + ((lane >> 4) & 1) * 8;
    const uint32_t b_base = (uint32_t)(b_row * 128 + ((lane >> 3) & 1) * 16);
    const uint32_t b_mask = (uint32_t)((b_row & 7) << 4);

    float am[2][4][4];   // main accumulators
    float ac[2][4][4];   // correction accumulators (scale 2048)
    #pragma unroll
    for (int mt = 0; mt < 2; mt++)
        #pragma unroll
        for (int nt = 0; nt < 4; nt++)
            #pragma unroll
            for (int q = 0; q < 4; q++) { am[mt][nt][q] = 0.f; ac[mt][nt][q] = 0.f; }

    // loader: 512 threads x 2 cpa16 per plane per chunk
    auto load_chunk = [&](int ch, int buf) {
        const uint32_t stage = sb + buf * STAGE_BYTES;
        const int k0 = ch * BK;
        #pragma unroll
        for (int j = 0; j < 2; j++) {
            const int u = tid * 2 + j;
            const int r = u >> 3;          // 0..127
            const int g = u & 7;           // 16B group in 128B row
            const uint32_t d = swz128((uint32_t)(r * 128 + g * 16));
            const size_t offA = ((size_t)(row0 + r) * KDIM + k0 + g * 8) * 2;
            const size_t offB = ((size_t)(col0 + r) * KDIM + k0 + g * 8) * 2;
            cpa16(stage + d,                   (const char*)g_xhi + offA);
            cpa16(stage + PLANE_BYTES + d,     (const char*)g_xlo + offA);
            cpa16(stage + 2 * PLANE_BYTES + d, (const char*)g_whi + offB);
            cpa16(stage + 3 * PLANE_BYTES + d, (const char*)g_wlo + offB);
        }
    };

    load_chunk(0, 0); cpa_commit();
    load_chunk(1, 1); cpa_commit();

    for (int ch = 0; ch < NCHUNK; ch++) {
        const int buf = ch % NSTAGE;
        if (ch + 1 < NCHUNK) cpa_wait<1>(); else cpa_wait<0>();
        __syncthreads();              // buffer `buf` ready; prev compute done
        if (ch + 2 < NCHUNK) {
            load_chunk(ch + 2, (ch + 2) % NSTAGE);
            cpa_commit();
        }

        const uint32_t st = sb + buf * STAGE_BYTES;
        #pragma unroll
        for (int ks = 0; ks < 4; ks++) {
            uint32_t Ah[2][4], Al[2][4];
            #pragma unroll
            for (int mt = 0; mt < 2; mt++) {
                const uint32_t au =
                    (a_base + (uint32_t)(mt * 2048 + ks * 32)) ^ a_mask;
                ldsm4(Ah[mt], st + au);
                ldsm4(Al[mt], st + PLANE_BYTES + au);
            }
            uint32_t Bh[4][2], Bl[4][2];
            #pragma unroll
            for (int pr = 0; pr < 2; pr++) {
                const uint32_t bu =
                    (b_base + (uint32_t)(pr * 2048 + ks * 32)) ^ b_mask;
                uint32_t r4[4];
                ldsm4(r4, st + 2 * PLANE_BYTES + bu);
                Bh[pr * 2][0] = r4[0]; Bh[pr * 2][1] = r4[1];
                Bh[pr * 2 + 1][0] = r4[2]; Bh[pr * 2 + 1][1] = r4[3];
                ldsm4(r4, st + 3 * PLANE_BYTES + bu);
                Bl[pr * 2][0] = r4[0]; Bl[pr * 2][1] = r4[1];
                Bl[pr * 2 + 1][0] = r4[2]; Bl[pr * 2 + 1][1] = r4[3];
            }
            #pragma unroll
            for (int mt = 0; mt < 2; mt++)
                #pragma unroll
                for (int nt = 0; nt < 4; nt++) {
                    mma_f16(am[mt][nt], Ah[mt], Bh[nt]);
                    mma_f16(ac[mt][nt], Ah[mt], Bl[nt]);
                    mma_f16(ac[mt][nt], Al[mt], Bh[nt]);
                }
        }
    }
    __syncthreads();

    // ---- epilogue: combine, exp, mask, store E, per-row sums ----
    float* srows = (float*)smem;   // [128][4] partial sums
    float rsl[2], rsh[2];
    #pragma unroll
    for (int mt = 0; mt < 2; mt++) { rsl[mt] = 0.f; rsh[mt] = 0.f; }

    #pragma unroll
    for (int mt = 0; mt < 2; mt++) {
        const int rl = warp_m * 32 + mt * 16 + (lane >> 2);
        #pragma unroll
        for (int nt = 0; nt < 4; nt++) {
            const int gc = col0 + warp_n * 32 + nt * 8 + (lane & 3) * 2;
            float e0 = expf(am[mt][nt][0] + ac[mt][nt][0] * LO_INV);
            float e1 = expf(am[mt][nt][1] + ac[mt][nt][1] * LO_INV);
            float e2 = expf(am[mt][nt][2] + ac[mt][nt][2] * LO_INV);
            float e3 = expf(am[mt][nt][3] + ac[mt][nt][3] * LO_INV);
            if (gc >= MEM)     { e0 = 0.f; e2 = 0.f; }
            if (gc + 1 >= MEM) { e1 = 0.f; e3 = 0.f; }
            const int growl = row0 + rl;
            *(float2*)(g_E + (size_t)growl * MPAD + gc) = make_float2(e0, e1);
            *(float2*)(g_E + (size_t)(growl + 8) * MPAD + gc) = make_float2(e2, e3);
            rsl[mt] += e0 + e1;
            rsh[mt] += e2 + e3;
        }
    }
    #pragma unroll
    for (int mt = 0; mt < 2; mt++) {
        #pragma unroll
        for (int o = 1; o <= 2; o <<= 1) {
            rsl[mt] += __shfl_xor_sync(FULL_MASK, rsl[mt], o);
            rsh[mt] += __shfl_xor_sync(FULL_MASK, rsh[mt], o);
        }
    }
    if ((lane & 3) == 0) {
        #pragma unroll
        for (int mt = 0; mt < 2; mt++) {
            const int rl = warp_m * 32 + mt * 16 + (lane >> 2);
            srows[rl * 4 + warp_n] = rsl[mt];
            srows[(rl + 8) * 4 + warp_n] = rsh[mt];
        }
    }
    __syncthreads();
    if (tid < 128) {
        const float z = srows[tid * 4 + 0] + srows[tid * 4 + 1] +
                        srows[tid * 4 + 2] + srows[tid * 4 + 3];
        g_Zp[blockIdx.x * NROWS + row0 + tid] = z;
    }
}

// ---------------------------------------------------------------------------
// K2: per row (1 warp/row): single E read (cached in regs), Z, threshold,
//     survivor sum, att write, sparse out.
// ---------------------------------------------------------------------------
__global__ void __launch_bounds__(256)
k_finish(const float* __restrict__ w, float* __restrict__ out,
         float* __restrict__ att) {
    const int lane = threadIdx.x & 31;
    const int wid  = threadIdx.x >> 5;
    const int n    = blockIdx.x * 8 + wid;

    const float4* E4 = (const float4*)(g_E + (size_t)n * MPAD);

    float Z = 0.f;
    #pragma unroll
    for (int j = 0; j < NMBLK; j++) Z += g_Zp[j * NROWS + n];
    const float t = LAMBDA * Z;

    // single pass over E: cache in registers, survivor sum
    float4 ev[16];
    float s = 0.f;
    #pragma unroll
    for (int it = 0; it < 16; it++) {
        const int i = lane + 32 * it;
        float4 v = (i < MEM / 4) ? E4[i] : make_float4(0.f, 0.f, 0.f, 0.f);
        ev[it] = v;
        if (v.x > t) s += v.x;
        if (v.y > t) s += v.y;
        if (v.z > t) s += v.z;
        if (v.w > t) s += v.w;
    }
    #pragma unroll
    for (int o = 16; o; o >>= 1) s += __shfl_xor_sync(FULL_MASK, s, o);
    const float inv = (s > 0.f) ? (1.0f / s) : 0.f;

    float4* att4 = (float4*)(att + (size_t)n * MEM);
    float oacc[16];
    #pragma unroll
    for (int q = 0; q < 16; q++) oacc[q] = 0.f;

    #pragma unroll
    for (int it = 0; it < 16; it++) {
        const int i = lane + 32 * it;
        const bool active = (i < MEM / 4);
        float4 v = ev[it];
        float4 o;
        int m4 = 0;
        o.x = (v.x > t) ? v.x * inv : 0.f; if (v.x > t) m4 |= 1;
        o.y = (v.y > t) ? v.y * inv : 0.f; if (v.y > t) m4 |= 2;
        o.z = (v.z > t) ? v.z * inv : 0.f; if (v.z > t) m4 |= 4;
        o.w = (v.w > t) ? v.w * inv : 0.f; if (v.w > t) m4 |= 8;
        if (active) att4[i] = o;

        unsigned bal = __ballot_sync(FULL_MASK, m4 != 0);
        while (bal) {
            const int src = __ffs(bal) - 1;
            bal &= bal - 1;
            const int sm4 = __shfl_sync(FULL_MASK, m4, src);
            float av[4];
            av[0] = __shfl_sync(FULL_MASK, o.x, src);
            av[1] = __shfl_sync(FULL_MASK, o.y, src);
            av[2] = __shfl_sync(FULL_MASK, o.z, src);
            av[3] = __shfl_sync(FULL_MASK, o.w, src);
            const int mbase = 4 * (src + 32 * it);
            #pragma unroll
            for (int j = 0; j < 4; j++) {
                if (sm4 & (1 << j)) {
                    const float* wr = w + (size_t)(mbase + j) * KDIM;
                    const float a = av[j];
                    #pragma unroll
                    for (int q = 0; q < 16; q++)
                        oacc[q] += a * wr[lane + 32 * q];
                }
            }
        }
    }

    float* orow = out + (size_t)n * KDIM;
    #pragma unroll
    for (int q = 0; q < 16; q++) orow[lane + 32 * q] = oacc[q];
}

// ---------------------------------------------------------------------------
extern "C" void kernel_launch(void* const* d_in, const int* in_sizes, int n_in,
                              void* d_out, int out_size) {
    (void)in_sizes; (void)n_in; (void)out_size;
    const float* x = (const float*)d_in[0];
    const float* w = (const float*)d_in[1];
    float* out = (float*)d_out;
    float* att = (float*)d_out + (size_t)NROWS * KDIM;

    cudaFuncSetAttribute(k_gemm_mma,
                         cudaFuncAttributeMaxDynamicSharedMemorySize, SMEM_TOTAL);

    k_prep_x<<<(NROWS * KDIM / 4) / 256, 256>>>(x);
    k_prep_w<<<(MPAD * KDIM / 4) / 256, 256>>>(w);
    k_gemm_mma<<<dim3(MPAD / BN, NROWS / BM), 512, SMEM_TOTAL>>>();
    k_finish<<<NROWS / 8, 256>>>(w, out, att);
}